// round 3
// baseline (speedup 1.0000x reference)
#include <cuda_runtime.h>
#include <math.h>
#include <stdint.h>

#define BATCH 8
#define LPTS  2048
#define NPTS  (BATCH*LPTS)
#define HIN   20
#define K1    16
#define K2    32
#define NG    32
#define DM    128
#define DH    32

__device__ int   g_knn[NPTS * K2];
__device__ float g_heads[NPTS * 5];

// ---- Kernel A: exact top-32 NN (radix select + bitonic), sorted (d2,idx) asc
__global__ __launch_bounds__(256) void knn_kernel(const float* __restrict__ frames)
{
    __shared__ float scx[LPTS], scy[LPTS], scz[LPTS];
    __shared__ unsigned sd[LPTS];
    __shared__ unsigned hist[256];
    __shared__ unsigned s_prefix, s_krem;
    __shared__ int s_cntlt, s_cnteq;
    __shared__ unsigned s_selk[32];
    __shared__ int s_seli[32];
    __shared__ int s_tie[64];

    const int n = blockIdx.x;
    const int b = n >> 11;
    const int l = n & 2047;
    const int t = threadIdx.x;

    const float* fb = frames + (size_t)b * LPTS * 12;
    for (int j = t; j < LPTS; j += 256) {
        scx[j] = fb[j*12+0]; scy[j] = fb[j*12+1]; scz[j] = fb[j*12+2];
    }
    __syncthreads();

    const float xi = scx[l], yi = scy[l], zi = scz[l];
    const float sqi = __fadd_rn(__fadd_rn(__fmul_rn(xi,xi), __fmul_rn(yi,yi)), __fmul_rn(zi,zi));

    for (int j = t; j < LPTS; j += 256) {
        float xj = scx[j], yj = scy[j], zj = scz[j];
        float sqj = __fadd_rn(__fadd_rn(__fmul_rn(xj,xj), __fmul_rn(yj,yj)), __fmul_rn(zj,zj));
        float dot = __fadd_rn(__fadd_rn(__fmul_rn(xi,xj), __fmul_rn(yi,yj)), __fmul_rn(zi,zj));
        float d2  = __fadd_rn(__fadd_rn(sqi, sqj), __fmul_rn(-2.0f, dot));
        unsigned ub  = __float_as_uint(d2);
        sd[j] = (ub & 0x80000000u) ? ~ub : (ub | 0x80000000u);
    }
    if (t == 0) { s_prefix = 0u; s_krem = K2; }
    __syncthreads();

    for (int pass = 0; pass < 4; pass++) {
        const int shift = 24 - pass * 8;
        const unsigned maskHi = (pass == 0) ? 0u : (0xFFFFFFFFu << (shift + 8));
        hist[t] = 0;
        __syncthreads();
        const unsigned pref = s_prefix;
        for (int j = t; j < LPTS; j += 256) {
            unsigned key = sd[j];
            if ((key & maskHi) == pref) atomicAdd(&hist[(key >> shift) & 255u], 1u);
        }
        __syncthreads();
        if (t < 32) {
            const int lane = t;
            unsigned c[8]; unsigned tot = 0;
            #pragma unroll
            for (int m = 0; m < 8; m++) { c[m] = hist[lane*8+m]; tot += c[m]; }
            unsigned v = tot;
            #pragma unroll
            for (int off = 1; off < 32; off <<= 1) {
                unsigned u = __shfl_up_sync(0xffffffffu, v, off);
                if (lane >= off) v += u;
            }
            const unsigned excl = v - tot;
            const unsigned krem = s_krem;
            unsigned cum = excl; int found = -1; unsigned kb = 0;
            #pragma unroll
            for (int m = 0; m < 8; m++) {
                if (found < 0 && cum + c[m] >= krem && c[m] > 0) { found = m; kb = cum; }
                cum += c[m];
            }
            const unsigned ball = __ballot_sync(0xffffffffu, found >= 0 && excl < krem);
            const int wlz = __ffs(ball) - 1;
            const int sb       = __shfl_sync(0xffffffffu, lane*8 + found, wlz);
            const unsigned kbw = __shfl_sync(0xffffffffu, kb, wlz);
            if (lane == 0) {
                s_prefix = pref | ((unsigned)sb << shift);
                s_krem   = krem - kbw;
            }
        }
        __syncthreads();
    }

    const unsigned tau = s_prefix;
    const int needEq = (int)s_krem;
    if (t == 0) { s_cntlt = 0; s_cnteq = 0; }
    __syncthreads();

    for (int j = t; j < LPTS; j += 256) {
        unsigned key = sd[j];
        if (key < tau) {
            int p = atomicAdd(&s_cntlt, 1);
            s_selk[p] = key; s_seli[p] = j;
        } else if (key == tau) {
            int q = atomicAdd(&s_cnteq, 1);
            if (q < 64) s_tie[q] = j;
        }
    }
    __syncthreads();
    if (t == 0) {
        int cl = s_cntlt;
        int ce = s_cnteq; if (ce > 64) ce = 64;
        for (int r = 0; r < needEq; r++) {
            int best = 0x7fffffff, bi = 0;
            for (int q = 0; q < ce; q++) if (s_tie[q] < best) { best = s_tie[q]; bi = q; }
            s_tie[bi] = 0x7fffffff;
            s_selk[cl + r] = tau; s_seli[cl + r] = best;
        }
    }
    __syncthreads();

    if (t < 32) {
        unsigned key = s_selk[t]; int idx = s_seli[t];
        #pragma unroll
        for (int k = 2; k <= 32; k <<= 1) {
            #pragma unroll
            for (int j = k >> 1; j > 0; j >>= 1) {
                int partner = t ^ j;
                unsigned ok = __shfl_xor_sync(0xffffffffu, key, j);
                int      oi = __shfl_xor_sync(0xffffffffu, idx, j);
                bool up = ((t & k) == 0);
                bool keep_min = ((t < partner) == up);
                bool gt = (key > ok) || (key == ok && idx > oi);
                bool lt = (key < ok) || (key == ok && idx < oi);
                bool take = keep_min ? gt : lt;
                if (take) { key = ok; idx = oi; }
            }
        }
        g_knn[n * K2 + t] = idx;
    }
}

// ---- Kernel B: gaussian conv -> 640x128 GEMM -> emb -> 5 heads
__global__ __launch_bounds__(512) void stage1_kernel(
    const float* __restrict__ attr,   const float* __restrict__ frames,
    const int*   __restrict__ aaidx,
    const float* __restrict__ cent1,  const float* __restrict__ prec1,
    const float* __restrict__ opW,    const float* __restrict__ opB,
    const float* __restrict__ embW,   const float* __restrict__ embB,
    const float* __restrict__ betaW,  const float* __restrict__ betaB,
    const float* __restrict__ selfW,  const float* __restrict__ selfB,
    const float* __restrict__ crossW, const float* __restrict__ crossB,
    const float* __restrict__ nodefW, const float* __restrict__ nodefB)
{
    extern __shared__ float sm[];
    float* s_crd  = sm;                 // 16*16*8
    float* s_attr = s_crd  + 2048;      // 16*16*20
    float* s_g1   = s_attr + 5120;      // 16*16*32
    float* s_M    = s_g1   + 8192;      // 16*640
    float* s_F    = s_M    + 10240;     // 16*128

    const int tid  = threadIdx.x;
    const int w    = tid >> 5;
    const int lane = tid & 31;
    const int n    = blockIdx.x * 16 + w;
    const int b    = n >> 11;

    {   // coords (lanes 0..15) / attr gather (lanes 16..31)
        const int k  = lane & 15;
        const int j  = g_knn[n * K2 + k];
        const int jj = b * LPTS + j;
        if (lane < 16) {
            const float* fo = frames + (size_t)n  * 12;
            const float* fj = frames + (size_t)jj * 12;
            float dx = fj[0]-fo[0], dy = fj[1]-fo[1], dz = fj[2]-fo[2];
            float dist = sqrtf(dx*dx + dy*dy + dz*dz + 1e-12f);
            float e0 = dx*fo[3] + dy*fo[4]  + dz*fo[5];
            float e1 = dx*fo[6] + dy*fo[7]  + dz*fo[8];
            float e2 = dx*fo[9] + dy*fo[10] + dz*fo[11];
            float zz  = fo[9]*fj[9] + fo[10]*fj[10] + fo[11]*fj[11];
            float dzv = (dx*fj[9] + dy*fj[10] + dz*fj[11]) / dist;
            float zdv = (fo[9]*dx + fo[10]*dy + fo[11]*dz) / dist;
            float idist = fminf(fabsf((float)aaidx[jj] - (float)aaidx[n]), 8.0f);
            float* c = s_crd + (w*16 + k) * 8;
            c[0]=e0; c[1]=e1; c[2]=e2; c[3]=idist; c[4]=zz; c[5]=dzv; c[6]=zdv; c[7]=0.f;
        } else {
            const float* ap = attr + (size_t)jj * HIN;
            float* d = s_attr + (w*16 + k) * HIN;
            #pragma unroll
            for (int h = 0; h < HIN; h++) d[h] = ap[h];
        }
    }
    __syncwarp();

    {   // gaussians: lane = gaussian index
        float pr[49], ce[7];
        #pragma unroll
        for (int q = 0; q < 49; q++) pr[q] = prec1[q * NG + lane];
        #pragma unroll
        for (int d = 0; d < 7; d++) ce[d] = cent1[d * NG + lane];
        for (int k = 0; k < K1; k++) {
            const float4* cp = (const float4*)(s_crd + (w*16 + k) * 8);
            float4 a = cp[0], bq = cp[1];
            float diff[7] = { a.x-ce[0], a.y-ce[1], a.z-ce[2], a.w-ce[3],
                              bq.x-ce[4], bq.y-ce[5], bq.z-ce[6] };
            float acc = 0.f;
            #pragma unroll
            for (int kk = 0; kk < 7; kk++) {
                float y = 0.f;
                #pragma unroll
                for (int d = 0; d < 7; d++) y += diff[d] * pr[d*7 + kk];
                acc += y * y;
            }
            s_g1[(w*16 + k) * NG + lane] = __expf(-0.5f * acc);
        }
    }
    __syncwarp();

    {   // M[g][h] = sum_k g1[k][g]*attr[k][h], lane = g
        float m[20];
        #pragma unroll
        for (int h = 0; h < 20; h++) m[h] = 0.f;
        for (int k = 0; k < K1; k++) {
            float v = s_g1[(w*16 + k) * NG + lane];
            const float4* ap = (const float4*)(s_attr + (w*16 + k) * HIN);
            #pragma unroll
            for (int q = 0; q < 5; q++) {
                float4 a = ap[q];
                m[q*4+0] += v*a.x; m[q*4+1] += v*a.y;
                m[q*4+2] += v*a.z; m[q*4+3] += v*a.w;
            }
        }
        float* mp = s_M + w*640 + lane*20;
        #pragma unroll
        for (int h = 0; h < 20; h++) mp[h] = m[h];
    }
    __syncthreads();

    {   // block GEMM: filt = M(16x640) @ opW(640x128)
        const int o   = tid & 127;
        const int grp = tid >> 7;
        const float* mb = s_M + grp * 4 * 640;
        float a0=0.f, a1=0.f, a2=0.f, a3=0.f;
        #pragma unroll 4
        for (int gh = 0; gh < 640; gh += 4) {
            float4 v0 = *(const float4*)(mb + 0*640 + gh);
            float4 v1 = *(const float4*)(mb + 1*640 + gh);
            float4 v2 = *(const float4*)(mb + 2*640 + gh);
            float4 v3 = *(const float4*)(mb + 3*640 + gh);
            const float* wp = opW + (size_t)gh * DM + o;
            float w0 = wp[0], w1 = wp[DM], w2 = wp[2*DM], w3 = wp[3*DM];
            a0 += v0.x*w0; a1 += v1.x*w0; a2 += v2.x*w0; a3 += v3.x*w0;
            a0 += v0.y*w1; a1 += v1.y*w1; a2 += v2.y*w1; a3 += v3.y*w1;
            a0 += v0.z*w2; a1 += v1.z*w2; a2 += v2.z*w2; a3 += v3.z*w2;
            a0 += v0.w*w3; a1 += v1.w*w3; a2 += v2.w*w3; a3 += v3.w*w3;
        }
        const float bo = opB[o];
        s_F[(grp*4+0)*DM + o] = fmaxf(a0 + bo, 0.f);
        s_F[(grp*4+1)*DM + o] = fmaxf(a1 + bo, 0.f);
        s_F[(grp*4+2)*DM + o] = fmaxf(a2 + bo, 0.f);
        s_F[(grp*4+3)*DM + o] = fmaxf(a3 + bo, 0.f);
    }
    __syncthreads();

    {   // emb (lane = channel) + 5 heads via warp reductions
        float acc = embB[lane];
        const float* fp = s_F + w * DM;
        #pragma unroll
        for (int ob = 0; ob < DM; ob += 4) {
            float4 f = *(const float4*)(fp + ob);
            acc += f.x * embW[(ob+0)*DH + lane];
            acc += f.y * embW[(ob+1)*DH + lane];
            acc += f.z * embW[(ob+2)*DH + lane];
            acc += f.w * embW[(ob+3)*DH + lane];
        }
        float emb = fmaxf(acc, 0.f);
        float hb = emb * betaW[lane];
        float hs = emb * selfW[lane];
        float hc = emb * crossW[lane];
        float h0 = emb * nodefW[lane*2 + 0];
        float h1 = emb * nodefW[lane*2 + 1];
        #pragma unroll
        for (int off = 16; off > 0; off >>= 1) {
            hb += __shfl_xor_sync(0xffffffffu, hb, off);
            hs += __shfl_xor_sync(0xffffffffu, hs, off);
            hc += __shfl_xor_sync(0xffffffffu, hc, off);
            h0 += __shfl_xor_sync(0xffffffffu, h0, off);
            h1 += __shfl_xor_sync(0xffffffffu, h1, off);
        }
        if (lane == 0) {
            float* hp = g_heads + (size_t)n * 5;
            hp[0] = fmaxf(hb + betaB[0],  0.f);
            hp[1] = fmaxf(hs + selfB[0],  0.f);
            hp[2] = fmaxf(hc + crossB[0], 0.f);
            hp[3] = fmaxf(h0 + nodefB[0], 0.f);
            hp[4] = fmaxf(h1 + nodefB[1], 0.f);
        }
    }
}

// ---- Kernel C: gaussian attention over K2=32, warp per point
__global__ __launch_bounds__(256) void stage2_kernel(
    const float* __restrict__ frames, const int* __restrict__ aaidx,
    const float* __restrict__ cent2,  const float* __restrict__ prec2,
    const float* __restrict__ emb2W,  const float* __restrict__ emb2B,
    float* __restrict__ out)
{
    __shared__ float s_pr[NG * 28];
    __shared__ float s_ce[NG * 8];
    __shared__ float s_w2[NG];

    const int tid = threadIdx.x;
    for (int q = tid; q < 25 * NG; q += 256) {
        int n2 = q & 31, dk = q >> 5;
        s_pr[n2*28 + dk] = prec2[dk*NG + n2];
    }
    for (int q = tid; q < 5 * NG; q += 256) {
        int n2 = q & 31, d = q >> 5;
        s_ce[n2*8 + d] = cent2[d*NG + n2];
    }
    if (tid < NG) s_w2[tid] = emb2W[tid];
    __syncthreads();

    const int w = tid >> 5, lane = tid & 31;
    const int n = blockIdx.x * 8 + w;
    const int b = n >> 11, l = n & 2047;
    const int j  = g_knn[n * K2 + lane];
    const int jj = b * LPTS + j;

    const float* fo = frames + (size_t)n  * 12;
    const float* fj = frames + (size_t)jj * 12;
    float dx = fj[0]-fo[0], dy = fj[1]-fo[1], dzc = fj[2]-fo[2];
    float dist = sqrtf(dx*dx + dy*dy + dzc*dzc + 1e-12f);
    float zz  = fo[9]*fj[9] + fo[10]*fj[10] + fo[11]*fj[11];
    float dzv = (dx*fj[9] + dy*fj[10] + dzc*fj[11]) / dist;
    float zdv = (fo[9]*dx + fo[10]*dy + fo[11]*dzc) / dist;
    float idist = fminf(fabsf((float)aaidx[jj] - (float)aaidx[n]), 8.0f);
    float cd[5] = { dist, zz, dzv, zdv, idist };

    float gw = emb2B[0];
    for (int n2 = 0; n2 < NG; n2++) {
        float diff[5];
        #pragma unroll
        for (int d = 0; d < 5; d++) diff[d] = cd[d] - s_ce[n2*8 + d];
        float acc = 0.f;
        #pragma unroll
        for (int kk = 0; kk < 5; kk++) {
            float y = 0.f;
            #pragma unroll
            for (int d = 0; d < 5; d++) y += diff[d] * s_pr[n2*28 + d*5 + kk];
            acc += y * y;
        }
        gw += __expf(-0.5f * acc) * s_w2[n2];
    }
    gw = fmaxf(gw, 0.f);

    const float* hj = g_heads + (size_t)jj * 5;
    const float* hi = g_heads + (size_t)n  * 5;
    float beta = hi[0], satt = hi[1];
    float e = (j == l) ? satt : hj[2];
    float logit = beta * e;
    float mx = logit;
    #pragma unroll
    for (int off = 16; off > 0; off >>= 1)
        mx = fmaxf(mx, __shfl_xor_sync(0xffffffffu, mx, off));
    float wv = gw * __expf(logit - mx);
    float s = wv, n0 = wv * hj[3], n1 = wv * hj[4];
    #pragma unroll
    for (int off = 16; off > 0; off >>= 1) {
        s  += __shfl_xor_sync(0xffffffffu, s,  off);
        n0 += __shfl_xor_sync(0xffffffffu, n0, off);
        n1 += __shfl_xor_sync(0xffffffffu, n1, off);
    }
    if (lane == 0) {
        float inv = 1.f / (s + 1e-6f);
        out[n*2 + 0] = n0 * inv;
        out[n*2 + 1] = n1 * inv;
    }
}

extern "C" void kernel_launch(void* const* d_in, const int* in_sizes, int n_in,
                              void* d_out, int out_size)
{
    const float* attr    = (const float*)d_in[0];
    const float* frames  = (const float*)d_in[1];
    const int*   aaidx   = (const int*)  d_in[2];
    const float* cent1   = (const float*)d_in[3];
    const float* prec1   = (const float*)d_in[4];
    const float* opW     = (const float*)d_in[5];
    const float* opB     = (const float*)d_in[6];
    const float* embW    = (const float*)d_in[7];
    const float* embB    = (const float*)d_in[8];
    const float* betaW   = (const float*)d_in[9];
    const float* betaB   = (const float*)d_in[10];
    const float* selfW   = (const float*)d_in[11];
    const float* selfB   = (const float*)d_in[12];
    const float* crossW  = (const float*)d_in[13];
    const float* crossB  = (const float*)d_in[14];
    const float* nodefW  = (const float*)d_in[15];
    const float* nodefB  = (const float*)d_in[16];
    const float* cent2   = (const float*)d_in[17];
    const float* prec2   = (const float*)d_in[18];
    const float* emb2W   = (const float*)d_in[19];
    const float* emb2B   = (const float*)d_in[20];
    float* out = (float*)d_out;

    static int s_attr_set = 0;
    if (!s_attr_set) {
        cudaFuncSetAttribute(stage1_kernel,
                             cudaFuncAttributeMaxDynamicSharedMemorySize, 110592);
        s_attr_set = 1;
    }

    knn_kernel<<<NPTS, 256>>>(frames);
    stage1_kernel<<<NPTS / 16, 512, 110592>>>(
        attr, frames, aaidx, cent1, prec1, opW, opB, embW, embB,
        betaW, betaB, selfW, selfB, crossW, crossB, nodefW, nodefB);
    stage2_kernel<<<NPTS / 8, 256>>>(frames, aaidx, cent2, prec2, emb2W, emb2B, out);
}

// round 4
// speedup vs baseline: 1.2618x; 1.2618x over previous
#include <cuda_runtime.h>
#include <math.h>
#include <stdint.h>

#define BATCH 8
#define LPTS  2048
#define NPTS  (BATCH*LPTS)
#define HIN   20
#define K1    16
#define K2    32
#define NG    32
#define DM    128
#define DH    32

__device__ int   g_knn[NPTS * K2];
__device__ float g_heads[NPTS * 5];

__device__ __forceinline__ unsigned long long pk2(float lo, float hi) {
    unsigned long long r;
    asm("mov.b64 %0,{%1,%2};" : "=l"(r) : "f"(lo), "f"(hi));
    return r;
}
__device__ __forceinline__ unsigned long long fma2(unsigned long long a,
                                                   unsigned long long b,
                                                   unsigned long long c) {
    unsigned long long d;
    asm("fma.rn.f32x2 %0,%1,%2,%3;" : "=l"(d) : "l"(a), "l"(b), "l"(c));
    return d;
}
__device__ __forceinline__ float upk_sum(unsigned long long v) {
    float lo, hi;
    asm("mov.b64 {%0,%1},%2;" : "=f"(lo), "=f"(hi) : "l"(v));
    return lo + hi;
}

// ---- Kernel A: warp-per-query exact top-32 via shuffle insertion-select ----
// Warp list L: lane i holds i-th smallest packed key ((d2bits<<32)|idx).
// Exact (d2, idx)-ascending order == JAX top_k(-d2) semantics.
__global__ __launch_bounds__(512) void knn_kernel(const float* __restrict__ frames)
{
    __shared__ float4 sc[LPTS];   // x, y, z, |c|^2
    const int t = threadIdx.x;
    const int b  = blockIdx.x >> 7;          // 128 blocks per batch
    const int l0 = (blockIdx.x & 127) * 16;

    const float* fb = frames + (size_t)b * LPTS * 12;
    for (int j = t; j < LPTS; j += 512) {
        float x = fb[j*12+0], y = fb[j*12+1], z = fb[j*12+2];
        float sq = __fadd_rn(__fadd_rn(__fmul_rn(x,x), __fmul_rn(y,y)), __fmul_rn(z,z));
        sc[j] = make_float4(x, y, z, sq);
    }
    __syncthreads();

    const int w = t >> 5, lane = t & 31;
    const int l = l0 + w;
    const float4 q = sc[l];
    const float xi = q.x, yi = q.y, zi = q.z, sqi = q.w;

    unsigned long long L   = ~0ull;   // sentinel = +inf key
    unsigned long long thr = ~0ull;

    #pragma unroll 4
    for (int i = 0; i < 64; i++) {
        const int j = i * 32 + lane;
        const float4 c = sc[j];
        float dot = __fadd_rn(__fadd_rn(__fmul_rn(xi,c.x), __fmul_rn(yi,c.y)), __fmul_rn(zi,c.z));
        float d2  = __fadd_rn(__fadd_rn(sqi, c.w), __fmul_rn(-2.0f, dot));
        unsigned ub  = __float_as_uint(d2);
        unsigned key = (ub & 0x80000000u) ? ~ub : (ub | 0x80000000u);
        unsigned long long pk = ((unsigned long long)key << 32) | (unsigned)j;

        unsigned pending = __ballot_sync(0xffffffffu, pk < thr);
        while (pending) {
            const int src = __ffs(pending) - 1;
            const unsigned long long v = __shfl_sync(0xffffffffu, pk, src);
            const unsigned lt = __ballot_sync(0xffffffffu, L < v);
            const int pos = __popc(lt);
            const unsigned long long up = __shfl_up_sync(0xffffffffu, L, 1);
            if (lane == pos)      L = v;
            else if (lane > pos)  L = up;
            thr = __shfl_sync(0xffffffffu, L, 31);
            pending &= ~(1u << src);
            pending &= __ballot_sync(0xffffffffu, pk < thr);
        }
    }
    g_knn[(size_t)(b * LPTS + l) * K2 + lane] = (int)(L & 0xffffffffu);
}

// ---- Kernel B: gaussian conv -> 640x128 GEMM (f32x2) -> emb -> 5 heads ----
__global__ __launch_bounds__(512) void stage1_kernel(
    const float* __restrict__ attr,   const float* __restrict__ frames,
    const int*   __restrict__ aaidx,
    const float* __restrict__ cent1,  const float* __restrict__ prec1,
    const float* __restrict__ opW,    const float* __restrict__ opB,
    const float* __restrict__ embW,   const float* __restrict__ embB,
    const float* __restrict__ betaW,  const float* __restrict__ betaB,
    const float* __restrict__ selfW,  const float* __restrict__ selfB,
    const float* __restrict__ crossW, const float* __restrict__ crossB,
    const float* __restrict__ nodefW, const float* __restrict__ nodefB)
{
    extern __shared__ float sm[];
    float* s_crd  = sm;                 // 16*16*8
    float* s_attr = s_crd  + 2048;      // 16*16*20
    float* s_g1   = s_attr + 5120;      // 16*16*32
    float* s_M    = s_g1   + 8192;      // 16*640
    float* s_F    = s_M    + 10240;     // 16*128

    const int tid  = threadIdx.x;
    const int w    = tid >> 5;
    const int lane = tid & 31;
    const int n    = blockIdx.x * 16 + w;
    const int b    = n >> 11;

    {   // coords (lanes 0..15) / attr gather (lanes 16..31)
        const int k  = lane & 15;
        const int j  = g_knn[n * K2 + k];
        const int jj = b * LPTS + j;
        if (lane < 16) {
            const float* fo = frames + (size_t)n  * 12;
            const float* fj = frames + (size_t)jj * 12;
            float dx = fj[0]-fo[0], dy = fj[1]-fo[1], dz = fj[2]-fo[2];
            float dist = sqrtf(dx*dx + dy*dy + dz*dz + 1e-12f);
            float e0 = dx*fo[3] + dy*fo[4]  + dz*fo[5];
            float e1 = dx*fo[6] + dy*fo[7]  + dz*fo[8];
            float e2 = dx*fo[9] + dy*fo[10] + dz*fo[11];
            float zz  = fo[9]*fj[9] + fo[10]*fj[10] + fo[11]*fj[11];
            float dzv = (dx*fj[9] + dy*fj[10] + dz*fj[11]) / dist;
            float zdv = (fo[9]*dx + fo[10]*dy + fo[11]*dz) / dist;
            float idist = fminf(fabsf((float)aaidx[jj] - (float)aaidx[n]), 8.0f);
            float* c = s_crd + (w*16 + k) * 8;
            c[0]=e0; c[1]=e1; c[2]=e2; c[3]=idist; c[4]=zz; c[5]=dzv; c[6]=zdv; c[7]=0.f;
        } else {
            const float* ap = attr + (size_t)jj * HIN;
            float* d = s_attr + (w*16 + k) * HIN;
            #pragma unroll
            for (int h = 0; h < HIN; h++) d[h] = ap[h];
        }
    }
    __syncwarp();

    {   // gaussians: lane = gaussian index
        float pr[49], ce[7];
        #pragma unroll
        for (int qq = 0; qq < 49; qq++) pr[qq] = prec1[qq * NG + lane];
        #pragma unroll
        for (int d = 0; d < 7; d++) ce[d] = cent1[d * NG + lane];
        for (int k = 0; k < K1; k++) {
            const float4* cp = (const float4*)(s_crd + (w*16 + k) * 8);
            float4 a = cp[0], bq = cp[1];
            float diff[7] = { a.x-ce[0], a.y-ce[1], a.z-ce[2], a.w-ce[3],
                              bq.x-ce[4], bq.y-ce[5], bq.z-ce[6] };
            float acc = 0.f;
            #pragma unroll
            for (int kk = 0; kk < 7; kk++) {
                float y = 0.f;
                #pragma unroll
                for (int d = 0; d < 7; d++) y += diff[d] * pr[d*7 + kk];
                acc += y * y;
            }
            s_g1[(w*16 + k) * NG + lane] = __expf(-0.5f * acc);
        }
    }
    __syncwarp();

    {   // M[g][h] = sum_k g1[k][g]*attr[k][h], lane = g
        float m[20];
        #pragma unroll
        for (int h = 0; h < 20; h++) m[h] = 0.f;
        for (int k = 0; k < K1; k++) {
            float v = s_g1[(w*16 + k) * NG + lane];
            const float4* ap = (const float4*)(s_attr + (w*16 + k) * HIN);
            #pragma unroll
            for (int qq = 0; qq < 5; qq++) {
                float4 a = ap[qq];
                m[qq*4+0] += v*a.x; m[qq*4+1] += v*a.y;
                m[qq*4+2] += v*a.z; m[qq*4+3] += v*a.w;
            }
        }
        float* mp = s_M + w*640 + lane*20;
        #pragma unroll
        for (int h = 0; h < 20; h++) mp[h] = m[h];
    }
    __syncthreads();

    {   // block GEMM: filt = M(16x640) @ opW(640x128), packed f32x2
        const int o   = tid & 127;
        const int grp = tid >> 7;
        const float* mb = s_M + grp * 4 * 640;
        unsigned long long a0 = 0ull, a1 = 0ull, a2 = 0ull, a3 = 0ull;
        #pragma unroll 4
        for (int gh = 0; gh < 640; gh += 4) {
            ulonglong2 u0 = *(const ulonglong2*)(mb + 0*640 + gh);
            ulonglong2 u1 = *(const ulonglong2*)(mb + 1*640 + gh);
            ulonglong2 u2 = *(const ulonglong2*)(mb + 2*640 + gh);
            ulonglong2 u3 = *(const ulonglong2*)(mb + 3*640 + gh);
            const float* wp = opW + (size_t)gh * DM + o;
            unsigned long long w01 = pk2(wp[0],    wp[DM]);
            unsigned long long w23 = pk2(wp[2*DM], wp[3*DM]);
            a0 = fma2(u0.x, w01, a0); a0 = fma2(u0.y, w23, a0);
            a1 = fma2(u1.x, w01, a1); a1 = fma2(u1.y, w23, a1);
            a2 = fma2(u2.x, w01, a2); a2 = fma2(u2.y, w23, a2);
            a3 = fma2(u3.x, w01, a3); a3 = fma2(u3.y, w23, a3);
        }
        const float bo = opB[o];
        s_F[(grp*4+0)*DM + o] = fmaxf(upk_sum(a0) + bo, 0.f);
        s_F[(grp*4+1)*DM + o] = fmaxf(upk_sum(a1) + bo, 0.f);
        s_F[(grp*4+2)*DM + o] = fmaxf(upk_sum(a2) + bo, 0.f);
        s_F[(grp*4+3)*DM + o] = fmaxf(upk_sum(a3) + bo, 0.f);
    }
    __syncthreads();

    {   // emb (lane = channel) + 5 heads via warp reductions
        float acc = embB[lane];
        const float* fp = s_F + w * DM;
        #pragma unroll
        for (int ob = 0; ob < DM; ob += 4) {
            float4 f = *(const float4*)(fp + ob);
            acc += f.x * embW[(ob+0)*DH + lane];
            acc += f.y * embW[(ob+1)*DH + lane];
            acc += f.z * embW[(ob+2)*DH + lane];
            acc += f.w * embW[(ob+3)*DH + lane];
        }
        float emb = fmaxf(acc, 0.f);
        float hb = emb * betaW[lane];
        float hs = emb * selfW[lane];
        float hc = emb * crossW[lane];
        float h0 = emb * nodefW[lane*2 + 0];
        float h1 = emb * nodefW[lane*2 + 1];
        #pragma unroll
        for (int off = 16; off > 0; off >>= 1) {
            hb += __shfl_xor_sync(0xffffffffu, hb, off);
            hs += __shfl_xor_sync(0xffffffffu, hs, off);
            hc += __shfl_xor_sync(0xffffffffu, hc, off);
            h0 += __shfl_xor_sync(0xffffffffu, h0, off);
            h1 += __shfl_xor_sync(0xffffffffu, h1, off);
        }
        if (lane == 0) {
            float* hp = g_heads + (size_t)n * 5;
            hp[0] = fmaxf(hb + betaB[0],  0.f);
            hp[1] = fmaxf(hs + selfB[0],  0.f);
            hp[2] = fmaxf(hc + crossB[0], 0.f);
            hp[3] = fmaxf(h0 + nodefB[0], 0.f);
            hp[4] = fmaxf(h1 + nodefB[1], 0.f);
        }
    }
}

// ---- Kernel C: gaussian attention over K2=32, warp per point ----
__global__ __launch_bounds__(256) void stage2_kernel(
    const float* __restrict__ frames, const int* __restrict__ aaidx,
    const float* __restrict__ cent2,  const float* __restrict__ prec2,
    const float* __restrict__ emb2W,  const float* __restrict__ emb2B,
    float* __restrict__ out)
{
    __shared__ float s_pr[NG * 28];
    __shared__ float s_ce[NG * 8];
    __shared__ float s_w2[NG];

    const int tid = threadIdx.x;
    for (int q = tid; q < 25 * NG; q += 256) {
        int n2 = q & 31, dk = q >> 5;
        s_pr[n2*28 + dk] = prec2[dk*NG + n2];
    }
    for (int q = tid; q < 5 * NG; q += 256) {
        int n2 = q & 31, d = q >> 5;
        s_ce[n2*8 + d] = cent2[d*NG + n2];
    }
    if (tid < NG) s_w2[tid] = emb2W[tid];
    __syncthreads();

    const int w = tid >> 5, lane = tid & 31;
    const int n = blockIdx.x * 8 + w;
    const int b = n >> 11, l = n & 2047;
    const int j  = g_knn[n * K2 + lane];
    const int jj = b * LPTS + j;

    const float* fo = frames + (size_t)n  * 12;
    const float* fj = frames + (size_t)jj * 12;
    float dx = fj[0]-fo[0], dy = fj[1]-fo[1], dzc = fj[2]-fo[2];
    float dist = sqrtf(dx*dx + dy*dy + dzc*dzc + 1e-12f);
    float zz  = fo[9]*fj[9] + fo[10]*fj[10] + fo[11]*fj[11];
    float dzv = (dx*fj[9] + dy*fj[10] + dzc*fj[11]) / dist;
    float zdv = (fo[9]*dx + fo[10]*dy + fo[11]*dzc) / dist;
    float idist = fminf(fabsf((float)aaidx[jj] - (float)aaidx[n]), 8.0f);
    float cd[5] = { dist, zz, dzv, zdv, idist };

    float gw = emb2B[0];
    for (int n2 = 0; n2 < NG; n2++) {
        float diff[5];
        #pragma unroll
        for (int d = 0; d < 5; d++) diff[d] = cd[d] - s_ce[n2*8 + d];
        float acc = 0.f;
        #pragma unroll
        for (int kk = 0; kk < 5; kk++) {
            float y = 0.f;
            #pragma unroll
            for (int d = 0; d < 5; d++) y += diff[d] * s_pr[n2*28 + d*5 + kk];
            acc += y * y;
        }
        gw += __expf(-0.5f * acc) * s_w2[n2];
    }
    gw = fmaxf(gw, 0.f);

    const float* hj = g_heads + (size_t)jj * 5;
    const float* hi = g_heads + (size_t)n  * 5;
    float beta = hi[0], satt = hi[1];
    float e = (j == l) ? satt : hj[2];
    float logit = beta * e;
    float mx = logit;
    #pragma unroll
    for (int off = 16; off > 0; off >>= 1)
        mx = fmaxf(mx, __shfl_xor_sync(0xffffffffu, mx, off));
    float wv = gw * __expf(logit - mx);
    float s = wv, n0 = wv * hj[3], n1 = wv * hj[4];
    #pragma unroll
    for (int off = 16; off > 0; off >>= 1) {
        s  += __shfl_xor_sync(0xffffffffu, s,  off);
        n0 += __shfl_xor_sync(0xffffffffu, n0, off);
        n1 += __shfl_xor_sync(0xffffffffu, n1, off);
    }
    if (lane == 0) {
        float inv = 1.f / (s + 1e-6f);
        out[n*2 + 0] = n0 * inv;
        out[n*2 + 1] = n1 * inv;
    }
}

extern "C" void kernel_launch(void* const* d_in, const int* in_sizes, int n_in,
                              void* d_out, int out_size)
{
    const float* attr    = (const float*)d_in[0];
    const float* frames  = (const float*)d_in[1];
    const int*   aaidx   = (const int*)  d_in[2];
    const float* cent1   = (const float*)d_in[3];
    const float* prec1   = (const float*)d_in[4];
    const float* opW     = (const float*)d_in[5];
    const float* opB     = (const float*)d_in[6];
    const float* embW    = (const float*)d_in[7];
    const float* embB    = (const float*)d_in[8];
    const float* betaW   = (const float*)d_in[9];
    const float* betaB   = (const float*)d_in[10];
    const float* selfW   = (const float*)d_in[11];
    const float* selfB   = (const float*)d_in[12];
    const float* crossW  = (const float*)d_in[13];
    const float* crossB  = (const float*)d_in[14];
    const float* nodefW  = (const float*)d_in[15];
    const float* nodefB  = (const float*)d_in[16];
    const float* cent2   = (const float*)d_in[17];
    const float* prec2   = (const float*)d_in[18];
    const float* emb2W   = (const float*)d_in[19];
    const float* emb2B   = (const float*)d_in[20];
    float* out = (float*)d_out;

    static int s_attr_set = 0;
    if (!s_attr_set) {
        cudaFuncSetAttribute(stage1_kernel,
                             cudaFuncAttributeMaxDynamicSharedMemorySize, 110592);
        s_attr_set = 1;
    }

    knn_kernel<<<NPTS / 16, 512>>>(frames);
    stage1_kernel<<<NPTS / 16, 512, 110592>>>(
        attr, frames, aaidx, cent1, prec1, opW, opB, embW, embB,
        betaW, betaB, selfW, selfB, crossW, crossB, nodefW, nodefB);
    stage2_kernel<<<NPTS / 8, 256>>>(frames, aaidx, cent2, prec2, emb2W, emb2B, out);
}

// round 5
// speedup vs baseline: 1.3722x; 1.0875x over previous
#include <cuda_runtime.h>
#include <math.h>
#include <stdint.h>

#define BATCH 8
#define LPTS  2048
#define NPTS  (BATCH*LPTS)
#define HIN   20
#define K1    16
#define K2    32
#define NG    32
#define DM    128
#define DH    32

__device__ int   g_knn[NPTS * K2];
__device__ float g_heads[NPTS * 5];

__device__ __forceinline__ unsigned long long pk2(float lo, float hi) {
    unsigned long long r;
    asm("mov.b64 %0,{%1,%2};" : "=l"(r) : "f"(lo), "f"(hi));
    return r;
}
__device__ __forceinline__ unsigned long long fma2(unsigned long long a,
                                                   unsigned long long b,
                                                   unsigned long long c) {
    unsigned long long d;
    asm("fma.rn.f32x2 %0,%1,%2,%3;" : "=l"(d) : "l"(a), "l"(b), "l"(c));
    return d;
}
__device__ __forceinline__ float upk_sum(unsigned long long v) {
    float lo, hi;
    asm("mov.b64 {%0,%1},%2;" : "=f"(lo), "=f"(hi) : "l"(v));
    return lo + hi;
}

// ---- Kernel A: warp-per-query exact top-32, low-latency shuffle insert ----
__global__ __launch_bounds__(512) void knn_kernel(const float* __restrict__ frames)
{
    __shared__ float4 sc[LPTS];   // x, y, z, |c|^2
    const int t = threadIdx.x;
    const int b  = blockIdx.x >> 7;
    const int l0 = (blockIdx.x & 127) * 16;

    const float* fb = frames + (size_t)b * LPTS * 12;
    for (int j = t; j < LPTS; j += 512) {
        float x = fb[j*12+0], y = fb[j*12+1], z = fb[j*12+2];
        float sq = __fadd_rn(__fadd_rn(__fmul_rn(x,x), __fmul_rn(y,y)), __fmul_rn(z,z));
        sc[j] = make_float4(x, y, z, sq);
    }
    __syncthreads();

    const int w = t >> 5, lane = t & 31;
    const int l = l0 + w;
    const float4 q = sc[l];
    const float xi = q.x, yi = q.y, zi = q.z, sqi = q.w;

    unsigned long long L   = ~0ull;   // lane i = i-th smallest ((d2bits<<32)|idx)
    unsigned long long thr = ~0ull;

    #pragma unroll 4
    for (int i = 0; i < 64; i++) {
        const int j = i * 32 + lane;
        const float4 c = sc[j];
        float dot = __fadd_rn(__fadd_rn(__fmul_rn(xi,c.x), __fmul_rn(yi,c.y)), __fmul_rn(zi,c.z));
        float d2  = __fadd_rn(__fadd_rn(sqi, c.w), __fmul_rn(-2.0f, dot));
        unsigned ub  = __float_as_uint(d2);
        unsigned key = (ub & 0x80000000u) ? ~ub : (ub | 0x80000000u);
        unsigned long long pk = ((unsigned long long)key << 32) | (unsigned)j;

        unsigned pending = __ballot_sync(0xffffffffu, pk < thr);
        if (pending) {
            do {
                const int src = __ffs(pending) - 1;
                pending &= pending - 1;
                const unsigned long long v = __shfl_sync(0xffffffffu, pk, src);
                // ballot and shfl_up are independent -> short dep chain.
                const unsigned lt = __ballot_sync(0xffffffffu, L < v);
                const unsigned long long up = __shfl_up_sync(0xffffffffu, L, 1);
                const int pos = __popc(lt);   // pos==32 -> no-op (stale candidate)
                if (lane == pos)      L = v;
                else if (lane > pos)  L = up;
            } while (pending);
            thr = __shfl_sync(0xffffffffu, L, 31);
        }
    }
    g_knn[(size_t)(b * LPTS + l) * K2 + lane] = (int)(L & 0xffffffffu);
}

// ---- Kernel B: fused gaussian conv + M (f32x2) -> 640x128 GEMM -> heads ----
__global__ __launch_bounds__(512) void stage1_kernel(
    const float* __restrict__ attr,   const float* __restrict__ frames,
    const int*   __restrict__ aaidx,
    const float* __restrict__ cent1,  const float* __restrict__ prec1,
    const float* __restrict__ opW,    const float* __restrict__ opB,
    const float* __restrict__ embW,   const float* __restrict__ embB,
    const float* __restrict__ betaW,  const float* __restrict__ betaB,
    const float* __restrict__ selfW,  const float* __restrict__ selfB,
    const float* __restrict__ crossW, const float* __restrict__ crossB,
    const float* __restrict__ nodefW, const float* __restrict__ nodefB)
{
    extern __shared__ float sm[];
    float* s_crd  = sm;                 // 16*16*8   = 2048
    float* s_attr = s_crd  + 2048;      // 16*16*20  = 5120
    float* s_M    = s_attr + 5120;      // 16*640    = 10240
    float* s_F    = s_M    + 10240;     // 16*128    = 2048

    const int tid  = threadIdx.x;
    const int w    = tid >> 5;
    const int lane = tid & 31;
    const int n    = blockIdx.x * 16 + w;
    const int b    = n >> 11;

    {   // coords (lanes 0..15) / attr gather (lanes 16..31)
        const int k  = lane & 15;
        const int j  = g_knn[n * K2 + k];
        const int jj = b * LPTS + j;
        if (lane < 16) {
            const float* fo = frames + (size_t)n  * 12;
            const float* fj = frames + (size_t)jj * 12;
            float dx = fj[0]-fo[0], dy = fj[1]-fo[1], dz = fj[2]-fo[2];
            float dist = sqrtf(dx*dx + dy*dy + dz*dz + 1e-12f);
            float e0 = dx*fo[3] + dy*fo[4]  + dz*fo[5];
            float e1 = dx*fo[6] + dy*fo[7]  + dz*fo[8];
            float e2 = dx*fo[9] + dy*fo[10] + dz*fo[11];
            float zz  = fo[9]*fj[9] + fo[10]*fj[10] + fo[11]*fj[11];
            float dzv = (dx*fj[9] + dy*fj[10] + dz*fj[11]) / dist;
            float zdv = (fo[9]*dx + fo[10]*dy + fo[11]*dz) / dist;
            float idist = fminf(fabsf((float)aaidx[jj] - (float)aaidx[n]), 8.0f);
            float* c = s_crd + (w*16 + k) * 8;
            c[0]=e0; c[1]=e1; c[2]=e2; c[3]=idist; c[4]=zz; c[5]=dzv; c[6]=zdv; c[7]=0.f;
        } else {
            const float* ap = attr + (size_t)jj * HIN;
            float* d = s_attr + (w*16 + k) * HIN;
            #pragma unroll
            for (int h = 0; h < HIN; h++) d[h] = ap[h];
        }
    }
    __syncwarp();

    {   // fused: gaussians (lane = g) + M[g][h] accumulation, all f32x2
        unsigned long long pr2[21];   // kk pairs (0,1),(2,3),(4,5) per d
        float pr6[7], ce[7];
        #pragma unroll
        for (int d = 0; d < 7; d++) {
            #pragma unroll
            for (int p = 0; p < 3; p++)
                pr2[d*3+p] = pk2(prec1[(d*7 + 2*p)*NG + lane],
                                 prec1[(d*7 + 2*p + 1)*NG + lane]);
            pr6[d] = prec1[(d*7 + 6)*NG + lane];
            ce[d]  = cent1[d*NG + lane];
        }
        unsigned long long m2[10];
        #pragma unroll
        for (int h = 0; h < 10; h++) m2[h] = 0ull;

        for (int k = 0; k < K1; k++) {
            const float4* cp = (const float4*)(s_crd + (w*16 + k) * 8);
            float4 a = cp[0], bq = cp[1];
            float diff[7] = { a.x-ce[0], a.y-ce[1], a.z-ce[2], a.w-ce[3],
                              bq.x-ce[4], bq.y-ce[5], bq.z-ce[6] };
            unsigned long long y01 = 0ull, y23 = 0ull, y45 = 0ull;
            float y6 = 0.f;
            #pragma unroll
            for (int d = 0; d < 7; d++) {
                unsigned long long dd = pk2(diff[d], diff[d]);
                y01 = fma2(dd, pr2[d*3+0], y01);
                y23 = fma2(dd, pr2[d*3+1], y23);
                y45 = fma2(dd, pr2[d*3+2], y45);
                y6  = fmaf(diff[d], pr6[d], y6);
            }
            unsigned long long acc2 = fma2(y01, y01, fma2(y23, y23, fma2(y45, y45, 0ull)));
            float acc = upk_sum(acc2) + y6*y6;
            float gk = __expf(-0.5f * acc);
            unsigned long long gk2 = pk2(gk, gk);
            const ulonglong2* ap = (const ulonglong2*)(s_attr + (w*16 + k) * HIN);
            #pragma unroll
            for (int qq = 0; qq < 5; qq++) {
                ulonglong2 av = ap[qq];
                m2[qq*2+0] = fma2(gk2, av.x, m2[qq*2+0]);
                m2[qq*2+1] = fma2(gk2, av.y, m2[qq*2+1]);
            }
        }
        unsigned long long* mp = (unsigned long long*)(s_M + w*640 + lane*20);
        #pragma unroll
        for (int h = 0; h < 10; h++) mp[h] = m2[h];
    }
    __syncthreads();

    {   // block GEMM: filt = M(16x640) @ opW(640x128), packed f32x2
        const int o   = tid & 127;
        const int grp = tid >> 7;
        const float* mb = s_M + grp * 4 * 640;
        unsigned long long a0 = 0ull, a1 = 0ull, a2 = 0ull, a3 = 0ull;
        #pragma unroll 4
        for (int gh = 0; gh < 640; gh += 4) {
            ulonglong2 u0 = *(const ulonglong2*)(mb + 0*640 + gh);
            ulonglong2 u1 = *(const ulonglong2*)(mb + 1*640 + gh);
            ulonglong2 u2 = *(const ulonglong2*)(mb + 2*640 + gh);
            ulonglong2 u3 = *(const ulonglong2*)(mb + 3*640 + gh);
            const float* wp = opW + (size_t)gh * DM + o;
            unsigned long long w01 = pk2(wp[0],    wp[DM]);
            unsigned long long w23 = pk2(wp[2*DM], wp[3*DM]);
            a0 = fma2(u0.x, w01, a0); a0 = fma2(u0.y, w23, a0);
            a1 = fma2(u1.x, w01, a1); a1 = fma2(u1.y, w23, a1);
            a2 = fma2(u2.x, w01, a2); a2 = fma2(u2.y, w23, a2);
            a3 = fma2(u3.x, w01, a3); a3 = fma2(u3.y, w23, a3);
        }
        const float bo = opB[o];
        s_F[(grp*4+0)*DM + o] = fmaxf(upk_sum(a0) + bo, 0.f);
        s_F[(grp*4+1)*DM + o] = fmaxf(upk_sum(a1) + bo, 0.f);
        s_F[(grp*4+2)*DM + o] = fmaxf(upk_sum(a2) + bo, 0.f);
        s_F[(grp*4+3)*DM + o] = fmaxf(upk_sum(a3) + bo, 0.f);
    }
    __syncthreads();

    {   // emb (lane = channel) + 5 heads via warp reductions
        float acc = embB[lane];
        const float* fp = s_F + w * DM;
        #pragma unroll
        for (int ob = 0; ob < DM; ob += 4) {
            float4 f = *(const float4*)(fp + ob);
            acc += f.x * embW[(ob+0)*DH + lane];
            acc += f.y * embW[(ob+1)*DH + lane];
            acc += f.z * embW[(ob+2)*DH + lane];
            acc += f.w * embW[(ob+3)*DH + lane];
        }
        float emb = fmaxf(acc, 0.f);
        float hb = emb * betaW[lane];
        float hs = emb * selfW[lane];
        float hc = emb * crossW[lane];
        float h0 = emb * nodefW[lane*2 + 0];
        float h1 = emb * nodefW[lane*2 + 1];
        #pragma unroll
        for (int off = 16; off > 0; off >>= 1) {
            hb += __shfl_xor_sync(0xffffffffu, hb, off);
            hs += __shfl_xor_sync(0xffffffffu, hs, off);
            hc += __shfl_xor_sync(0xffffffffu, hc, off);
            h0 += __shfl_xor_sync(0xffffffffu, h0, off);
            h1 += __shfl_xor_sync(0xffffffffu, h1, off);
        }
        if (lane == 0) {
            float* hp = g_heads + (size_t)n * 5;
            hp[0] = fmaxf(hb + betaB[0],  0.f);
            hp[1] = fmaxf(hs + selfB[0],  0.f);
            hp[2] = fmaxf(hc + crossB[0], 0.f);
            hp[3] = fmaxf(h0 + nodefB[0], 0.f);
            hp[4] = fmaxf(h1 + nodefB[1], 0.f);
        }
    }
}

// ---- Kernel C: gaussian attention over K2=32, warp per point, f32x2 ----
__global__ __launch_bounds__(256) void stage2_kernel(
    const float* __restrict__ frames, const int* __restrict__ aaidx,
    const float* __restrict__ cent2,  const float* __restrict__ prec2,
    const float* __restrict__ emb2W,  const float* __restrict__ emb2B,
    float* __restrict__ out)
{
    __shared__ unsigned long long s_pr2[NG * 5 * 2];  // [n2][d][kk pair]
    __shared__ float s_pr4[NG * 5];                   // kk=4
    __shared__ float s_ce[NG * 8];
    __shared__ float s_w2[NG];

    const int tid = threadIdx.x;
    for (int q = tid; q < NG * 5; q += 256) {
        int n2 = q & 31, d = q >> 5;
        s_pr2[(n2*5+d)*2+0] = pk2(prec2[(d*5+0)*NG + n2], prec2[(d*5+1)*NG + n2]);
        s_pr2[(n2*5+d)*2+1] = pk2(prec2[(d*5+2)*NG + n2], prec2[(d*5+3)*NG + n2]);
        s_pr4[n2*5+d]       = prec2[(d*5+4)*NG + n2];
    }
    for (int q = tid; q < 5 * NG; q += 256) {
        int n2 = q & 31, d = q >> 5;
        s_ce[n2*8 + d] = cent2[d*NG + n2];
    }
    if (tid < NG) s_w2[tid] = emb2W[tid];
    __syncthreads();

    const int w = tid >> 5, lane = tid & 31;
    const int n = blockIdx.x * 8 + w;
    const int b = n >> 11, l = n & 2047;
    const int j  = g_knn[n * K2 + lane];
    const int jj = b * LPTS + j;

    const float* fo = frames + (size_t)n  * 12;
    const float* fj = frames + (size_t)jj * 12;
    float dx = fj[0]-fo[0], dy = fj[1]-fo[1], dzc = fj[2]-fo[2];
    float dist = sqrtf(dx*dx + dy*dy + dzc*dzc + 1e-12f);
    float zz  = fo[9]*fj[9] + fo[10]*fj[10] + fo[11]*fj[11];
    float dzv = (dx*fj[9] + dy*fj[10] + dzc*fj[11]) / dist;
    float zdv = (fo[9]*dx + fo[10]*dy + fo[11]*dzc) / dist;
    float idist = fminf(fabsf((float)aaidx[jj] - (float)aaidx[n]), 8.0f);
    float cd[5] = { dist, zz, dzv, zdv, idist };

    float gw = emb2B[0];
    #pragma unroll 4
    for (int n2 = 0; n2 < NG; n2++) {
        unsigned long long y01 = 0ull, y23 = 0ull;
        float y4 = 0.f;
        #pragma unroll
        for (int d = 0; d < 5; d++) {
            float df = cd[d] - s_ce[n2*8 + d];
            unsigned long long dd = pk2(df, df);
            y01 = fma2(dd, s_pr2[(n2*5+d)*2+0], y01);
            y23 = fma2(dd, s_pr2[(n2*5+d)*2+1], y23);
            y4  = fmaf(df, s_pr4[n2*5+d], y4);
        }
        unsigned long long acc2 = fma2(y01, y01, fma2(y23, y23, 0ull));
        float acc = upk_sum(acc2) + y4*y4;
        gw += __expf(-0.5f * acc) * s_w2[n2];
    }
    gw = fmaxf(gw, 0.f);

    const float* hj = g_heads + (size_t)jj * 5;
    const float* hi = g_heads + (size_t)n  * 5;
    float beta = hi[0], satt = hi[1];
    float e = (j == l) ? satt : hj[2];
    float logit = beta * e;
    float mx = logit;
    #pragma unroll
    for (int off = 16; off > 0; off >>= 1)
        mx = fmaxf(mx, __shfl_xor_sync(0xffffffffu, mx, off));
    float wv = gw * __expf(logit - mx);
    float s = wv, n0 = wv * hj[3], n1 = wv * hj[4];
    #pragma unroll
    for (int off = 16; off > 0; off >>= 1) {
        s  += __shfl_xor_sync(0xffffffffu, s,  off);
        n0 += __shfl_xor_sync(0xffffffffu, n0, off);
        n1 += __shfl_xor_sync(0xffffffffu, n1, off);
    }
    if (lane == 0) {
        float inv = 1.f / (s + 1e-6f);
        out[n*2 + 0] = n0 * inv;
        out[n*2 + 1] = n1 * inv;
    }
}

extern "C" void kernel_launch(void* const* d_in, const int* in_sizes, int n_in,
                              void* d_out, int out_size)
{
    const float* attr    = (const float*)d_in[0];
    const float* frames  = (const float*)d_in[1];
    const int*   aaidx   = (const int*)  d_in[2];
    const float* cent1   = (const float*)d_in[3];
    const float* prec1   = (const float*)d_in[4];
    const float* opW     = (const float*)d_in[5];
    const float* opB     = (const float*)d_in[6];
    const float* embW    = (const float*)d_in[7];
    const float* embB    = (const float*)d_in[8];
    const float* betaW   = (const float*)d_in[9];
    const float* betaB   = (const float*)d_in[10];
    const float* selfW   = (const float*)d_in[11];
    const float* selfB   = (const float*)d_in[12];
    const float* crossW  = (const float*)d_in[13];
    const float* crossB  = (const float*)d_in[14];
    const float* nodefW  = (const float*)d_in[15];
    const float* nodefB  = (const float*)d_in[16];
    const float* cent2   = (const float*)d_in[17];
    const float* prec2   = (const float*)d_in[18];
    const float* emb2W   = (const float*)d_in[19];
    const float* emb2B   = (const float*)d_in[20];
    float* out = (float*)d_out;

    static int s_attr_set = 0;
    if (!s_attr_set) {
        cudaFuncSetAttribute(stage1_kernel,
                             cudaFuncAttributeMaxDynamicSharedMemorySize, 77824);
        s_attr_set = 1;
    }

    knn_kernel<<<NPTS / 16, 512>>>(frames);
    stage1_kernel<<<NPTS / 16, 512, 77824>>>(
        attr, frames, aaidx, cent1, prec1, opW, opB, embW, embB,
        betaW, betaB, selfW, selfB, crossW, crossB, nodefW, nodefB);
    stage2_kernel<<<NPTS / 8, 256>>>(frames, aaidx, cent2, prec2, emb2W, emb2B, out);
}